// round 16
// baseline (speedup 1.0000x reference)
#include <cuda_runtime.h>
#include <cuda_bf16.h>
#include <cstdint>

#define PI_F 3.14159265358979323846f

// ---------------- device scratch (__device__ globals: sanctioned) ----------
__device__ float g_gate[16 * 16 * 16 * 8];                            // [b][ph][pw][e]
__device__ __align__(128) __nv_bfloat16 g_xh[16ULL * 130 * 130 * 64]; // NHWC hi
__device__ __align__(128) __nv_bfloat16 g_xl[16ULL * 130 * 130 * 64]; // NHWC lo
__device__ __align__(128) __nv_bfloat16 g_wA[9 * 4 * 2 * 128 * 64];   // [tap][mb][pl][ml][c]

// ---------------- PTX helpers (plain sm_80+ ISA, compute_103-safe) ---------
__device__ __forceinline__ void cp16(uint32_t dst, const void* src) {
    asm volatile("cp.async.ca.shared.global [%0], [%1], 16;"
                 :: "r"(dst), "l"(src) : "memory");
}
__device__ __forceinline__ void ldsm4(uint32_t* r, uint32_t addr) {
    asm volatile("ldmatrix.sync.aligned.m8n8.x4.shared.b16 {%0,%1,%2,%3}, [%4];"
                 : "=r"(r[0]), "=r"(r[1]), "=r"(r[2]), "=r"(r[3])
                 : "r"(addr));
}
__device__ __forceinline__ void mma16816(float* c, const uint32_t* a,
                                         const uint32_t* b) {
    asm volatile(
        "mma.sync.aligned.m16n8k16.row.col.f32.bf16.bf16.f32 "
        "{%0,%1,%2,%3}, {%4,%5,%6,%7}, {%8,%9}, {%0,%1,%2,%3};"
        : "+f"(c[0]), "+f"(c[1]), "+f"(c[2]), "+f"(c[3])
        : "r"(a[0]), "r"(a[1]), "r"(a[2]), "r"(a[3]), "r"(b[0]), "r"(b[1]));
}

// ---------------------------------------------------------------------------
// prep_x: x[b][c][y][x] fp32 -> padded NHWC bf16 hi/lo: [b][yp 130][xp 130][c]
// ---------------------------------------------------------------------------
__global__ void prep_x(const float* __restrict__ x) {
    __shared__ float tile[64][128];
    const int yp = blockIdx.x;       // 0..129
    const int b = blockIdx.y;
    const int tid = threadIdx.x;
    const bool rowok = (yp >= 1 && yp <= 128);
    if (rowok) {
        const float* src = x + ((size_t)b * 64 * 128 + (yp - 1)) * 128;
        for (int i = tid; i < 8192; i += 256) {
            int c = i >> 7, xx = i & 127;
            tile[c][xx] = src[c * 16384 + xx];
        }
    }
    __syncthreads();
    const size_t obase = ((size_t)b * 130 + yp) * 130 * 64;
    for (int i = tid; i < 130 * 64; i += 256) {
        int xp = i >> 6, c = i & 63;
        float v = 0.f;
        if (rowok && xp >= 1 && xp <= 128) v = tile[c][xp - 1];
        __nv_bfloat16 hi = __float2bfloat16(v);
        __nv_bfloat16 lo = __float2bfloat16(v - __bfloat162float(hi));
        g_xh[obase + i] = hi;
        g_xl[obase + i] = lo;
    }
}

// ---------------------------------------------------------------------------
// prep_w: ew[e][oc][c][dy][dx] -> g_wA[tap][mb][plane][ml][c] bf16 hi/lo
//         ml = eloc*64 + oc,  e = mb*2 + eloc
// ---------------------------------------------------------------------------
__global__ void prep_w(const float* __restrict__ ew) {
    int idx = blockIdx.x * 256 + threadIdx.x;   // < 294912
    int c = idx & 63;
    int ml = (idx >> 6) & 127;
    int mb = (idx >> 13) & 3;
    int tap = idx >> 15;
    int e = mb * 2 + (ml >> 6);
    int oc = ml & 63;
    int dy = tap / 3, dx = tap % 3;
    float w = ew[(((e * 64 + oc) * 64 + c) * 3 + dy) * 3 + dx];
    __nv_bfloat16 hi = __float2bfloat16(w);
    __nv_bfloat16 lo = __float2bfloat16(w - __bfloat162float(hi));
    size_t o = (size_t)(tap * 4 + mb) * 16384 + ml * 64 + c;
    g_wA[o] = hi;             // plane 0
    g_wA[o + 8192] = lo;      // plane 1
}

// ---------------------------------------------------------------------------
// gate kernel (proven correct, ~60us)
// ---------------------------------------------------------------------------
__global__ void gate_kernel(const float* __restrict__ x,
                            const float* __restrict__ gate_w,
                            const float* __restrict__ gate_b) {
    const int blk = blockIdx.x;
    const int b = blk >> 8;
    const int ph = (blk >> 4) & 15;
    const int pw = blk & 15;
    const int tid = threadIdx.x;

    float part[8];
#pragma unroll
    for (int e = 0; e < 8; e++) part[e] = 0.f;

    const float* xb = x + ((size_t)b * 64 * 128 + ph * 8) * 128 + pw * 8;

    for (int f = tid; f < 6144; f += 256) {
        int c = f >> 6;
        int r = f & 63;
        float v;
        if (c < 64) {
            int py = r >> 3, px = r & 7;
            v = xb[(c * 128 + py) * 128 + px];
        } else {
            int cc = c - 64;
            int grp = cc >> 3, k = cc & 7;
            float coord = (grp < 2) ? (ph + 0.5f) * (1.f / 16.f)
                                    : (pw + 0.5f) * (1.f / 16.f);
            float ang = coord * ((float)(1 << k) * PI_F);
            v = (grp & 1) ? cosf(ang) : sinf(ang);
        }
#pragma unroll
        for (int e = 0; e < 8; e++) part[e] += v * gate_w[e * 6144 + f];
    }

#pragma unroll
    for (int off = 16; off; off >>= 1) {
#pragma unroll
        for (int e = 0; e < 8; e++)
            part[e] += __shfl_down_sync(0xffffffffu, part[e], off);
    }

    __shared__ float s_red[8][8];
    __shared__ float s_logit[8];
    const int warp = tid >> 5, lane = tid & 31;
    if (lane == 0) {
#pragma unroll
        for (int e = 0; e < 8; e++) s_red[warp][e] = part[e];
    }
    __syncthreads();
    if (tid < 8) {
        float s = gate_b[tid];
#pragma unroll
        for (int w = 0; w < 8; w++) s += s_red[w][tid];
        s_logit[tid] = s;
    }
    __syncthreads();
    if (tid < 8) {
        float m = s_logit[0];
#pragma unroll
        for (int e = 1; e < 8; e++) m = fmaxf(m, s_logit[e]);
        float den = 0.f;
#pragma unroll
        for (int e = 0; e < 8; e++) den += expf(s_logit[e] - m);
        g_gate[blk * 8 + tid] = expf(s_logit[tid] - m) / den;
    }
}

// ---------------------------------------------------------------------------
// conv_mma: HMMA (mma.sync bf16) implicit-GEMM conv + bias + relu + gated
// combine. CTA = (row y, batch b): N = 128 pixels, M = 128 per phase, 4
// mblock phases (2 experts each) x 9 taps = 36 double-buffered stages.
// 512 threads = 16 warps in a 4(M) x 4(N) grid; warp tile M32 x N32 ->
// 8 mma tiles, 32 fp32 acc (4 warps/SMSP for latency hiding).
// 3 hi/lo passes per k16: Wh*Xh + Wl*Xh + Wh*Xl. Per-phase epilogue folds
// bias+relu+gate into a 64KB SMEM accumulator (per-thread slots, race-free);
// final sum over expert-parity planes -> single float4 store. No atomics.
// SMEM (dyn): A0|A1 (32KB ea) | B0|B1 (32KB ea) | acc 64KB.
// Swizzle: chunk j of row r stored at r*128 + ((j^(r&7))<<4)  (conflict-free
// for both cp.async stores and ldmatrix reads).
// ---------------------------------------------------------------------------
static constexpr int SACC_OFF = 131072;
static constexpr int DSMEM_BYTES = 131072 + 65536 + 1024;   // 197632

__global__ void __launch_bounds__(512, 1)
conv_mma(const float* __restrict__ eb, float* __restrict__ out) {
    extern __shared__ char dsm_raw[];
    __shared__ float sg[1024];      // [e][x]
    __shared__ float sbias[512];    // [e*64+oc]

    const int tid = threadIdx.x;
    const int wid = tid >> 5;
    const int lane = tid & 31;
    const int y = blockIdx.x;
    const int b = blockIdx.y;
    const int wm = wid >> 2;        // 0..3 : M quarter (32 rows)
    const int wn = wid & 3;         // 0..3 : N quarter (32 px)

    uint32_t base0 = (uint32_t)__cvta_generic_to_shared(dsm_raw);
    const uint32_t base = (base0 + 1023) & ~1023u;
    float* sacc = reinterpret_cast<float*>(dsm_raw + (base - base0) + SACC_OFF);

    for (int i = tid; i < 1024; i += 512) {
        int e = i >> 7, xx = i & 127;
        sg[i] = g_gate[(((b * 16 + (y >> 3)) * 16 + (xx >> 3)) << 3) + e];
    }
    if (tid < 512) sbias[tid] = eb[tid];
    for (int i = tid; i < 16384; i += 512) sacc[i] = 0.f;

    auto prefetch = [&](int s) {
        const int mb = s / 9, tap = s % 9;
        // A: W[tap][mb] hi/lo, contiguous 32KB in g_wA
        uint32_t abuf = base + (s & 1) * 32768;
        const __nv_bfloat16* asrc = g_wA + (size_t)(tap * 4 + mb) * 16384;
        for (int i = tid; i < 2048; i += 512) {
            int row = i >> 3, j = i & 7;          // row = plane*128 + ml
            cp16(abuf + row * 128 + ((j ^ (row & 7)) << 4),
                 asrc + row * 64 + j * 8);
        }
        // B: X row (y+dy), pixels dx..dx+127, hi/lo planes
        uint32_t bbuf = base + 65536 + (s & 1) * 32768;
        const int dy = tap / 3, dx = tap % 3;
        const size_t xoff = (((size_t)b * 130 + (y + dy)) * 130 + dx) * 64;
        for (int i = tid; i < 2048; i += 512) {
            int row = i >> 3, j = i & 7;          // row = plane*128 + pixel
            int plane = row >> 7, p = row & 127;
            const __nv_bfloat16* src =
                (plane ? g_xl : g_xh) + xoff + (size_t)p * 64 + j * 8;
            cp16(bbuf + row * 128 + ((j ^ (row & 7)) << 4), src);
        }
        asm volatile("cp.async.commit_group;" ::: "memory");
    };

    float acc[2][4][4];
#pragma unroll
    for (int mt = 0; mt < 2; mt++)
#pragma unroll
        for (int nt = 0; nt < 4; nt++)
#pragma unroll
            for (int v = 0; v < 4; v++) acc[mt][nt][v] = 0.f;

    const int lo4 = lane & 15;      // A: row selector within m16
    const int hi4 = lane >> 4;      // A: k-chunk selector / B: pixel+8 sel

    prefetch(0);

#pragma unroll 1
    for (int s = 0; s < 36; s++) {
        if (s + 1 < 36) {
            prefetch(s + 1);
            asm volatile("cp.async.wait_group 1;" ::: "memory");
        } else {
            asm volatile("cp.async.wait_group 0;" ::: "memory");
        }
        __syncthreads();

        const uint32_t ab = base + (s & 1) * 32768;
        const uint32_t bb = base + 65536 + (s & 1) * 32768;

#pragma unroll
        for (int kk = 0; kk < 4; kk++) {          // k0 = kk*16
            const int j0 = kk * 2;                // 16B chunk of k0
            uint32_t Ah[2][4], Al[2][4];
#pragma unroll
            for (int mt = 0; mt < 2; mt++) {
                int row = wm * 32 + mt * 16 + lo4;
                uint32_t off =
                    row * 128 + (((j0 + hi4) ^ (row & 7)) << 4);
                ldsm4(Ah[mt], ab + off);
                ldsm4(Al[mt], ab + 16384 + off);
            }
            uint32_t Bh[8], Bl[8];
#pragma unroll
            for (int half = 0; half < 2; half++) {
                int p = wn * 32 + half * 16 + (lane & 7) + hi4 * 8;
                int ch = j0 + ((lane >> 3) & 1);
                uint32_t off = p * 128 + ((ch ^ (p & 7)) << 4);
                ldsm4(Bh + half * 4, bb + off);
                ldsm4(Bl + half * 4, bb + 16384 + off);
            }
#pragma unroll
            for (int mt = 0; mt < 2; mt++) {
#pragma unroll
                for (int nt = 0; nt < 4; nt++) {
                    mma16816(acc[mt][nt], Ah[mt], Bh + nt * 2);
                    mma16816(acc[mt][nt], Al[mt], Bh + nt * 2);
                    mma16816(acc[mt][nt], Ah[mt], Bl + nt * 2);
                }
            }
        }
        __syncthreads();

        if (s % 9 == 8) {
            // per-mblock epilogue: bias + relu + gate into sacc, reset acc
            const int mb = s / 9;
#pragma unroll
            for (int mt = 0; mt < 2; mt++) {
                int mrow0 = wm * 32 + mt * 16 + (lane >> 2);
#pragma unroll
                for (int half = 0; half < 2; half++) {
                    int m = mrow0 + half * 8;
                    int eloc = m >> 6, oc = m & 63;
                    int e = mb * 2 + eloc;
                    float bias = sbias[e * 64 + oc];
                    const float* grow = sg + e * 128;
                    float* arow = sacc + eloc * 8192 + oc * 128;
#pragma unroll
                    for (int nt = 0; nt < 4; nt++) {
                        int n = wn * 32 + nt * 8 + (lane & 3) * 2;
                        float v0 = acc[mt][nt][half * 2 + 0];
                        float v1 = acc[mt][nt][half * 2 + 1];
                        arow[n]     += grow[n]     * fmaxf(v0 + bias, 0.f);
                        arow[n + 1] += grow[n + 1] * fmaxf(v1 + bias, 0.f);
                        acc[mt][nt][half * 2 + 0] = 0.f;
                        acc[mt][nt][half * 2 + 1] = 0.f;
                    }
                }
            }
        }
    }

    __syncthreads();
    const size_t ob = (size_t)b * 64 * 16384 + (size_t)y * 128;
    for (int i = tid; i < 2048; i += 512) {     // 64 oc x 32 float4
        int oc2 = i >> 5, j = i & 31;
        const float* r0 = sacc + oc2 * 128 + j * 4;
        const float* r1 = r0 + 8192;
        float4 v;
        v.x = r0[0] + r1[0];
        v.y = r0[1] + r1[1];
        v.z = r0[2] + r1[2];
        v.w = r0[3] + r1[3];
        *reinterpret_cast<float4*>(out + ob + (size_t)oc2 * 16384 + j * 4) = v;
    }
}

extern "C" void kernel_launch(void* const* d_in, const int* in_sizes, int n_in,
                              void* d_out, int out_size) {
    const float* x  = (const float*)d_in[0];   // [16,64,128,128]
    const float* ew = (const float*)d_in[1];   // [8,64,64,3,3]
    const float* eb = (const float*)d_in[2];   // [8,64]
    const float* gw = (const float*)d_in[3];   // [8,6144]
    const float* gb = (const float*)d_in[4];   // [8]
    float* out = (float*)d_out;                // [16,64,128,128]

    static bool attr_set = false;
    if (!attr_set) {
        cudaFuncSetAttribute(conv_mma,
                             cudaFuncAttributeMaxDynamicSharedMemorySize,
                             DSMEM_BYTES);
        attr_set = true;
    }

    prep_x<<<dim3(130, 16), 256>>>(x);
    prep_w<<<1152, 256>>>(ew);
    gate_kernel<<<4096, 256>>>(x, gw, gb);

    dim3 grid(128, 16);   // (row y, batch b)
    conv_mma<<<grid, 512, DSMEM_BYTES>>>(eb, out);
}

// round 17
// speedup vs baseline: 1.3323x; 1.3323x over previous
#include <cuda_runtime.h>
#include <cuda_fp16.h>
#include <cstdint>

#define PI_F 3.14159265358979323846f

// ---------------- device scratch (__device__ globals: sanctioned) ----------
__device__ float g_gate[16 * 16 * 16 * 8];                        // [b][ph][pw][e]
__device__ __align__(128) __half g_xh[16ULL * 130 * 130 * 64];    // NHWC hi
__device__ __align__(128) __half g_xl[16ULL * 130 * 130 * 64];    // NHWC lo (residual)
__device__ __align__(128) __half g_wA[9 * 4 * 128 * 64];          // [tap][mb][ml][c] fp16

// ---------------- PTX helpers (plain sm_80+ ISA, compute_103-safe) ---------
__device__ __forceinline__ void cp16(uint32_t dst, const void* src) {
    asm volatile("cp.async.ca.shared.global [%0], [%1], 16;"
                 :: "r"(dst), "l"(src) : "memory");
}
__device__ __forceinline__ void ldsm4(uint32_t* r, uint32_t addr) {
    asm volatile("ldmatrix.sync.aligned.m8n8.x4.shared.b16 {%0,%1,%2,%3}, [%4];"
                 : "=r"(r[0]), "=r"(r[1]), "=r"(r[2]), "=r"(r[3])
                 : "r"(addr));
}
__device__ __forceinline__ void mma16816(float* c, const uint32_t* a,
                                         const uint32_t* b) {
    asm volatile(
        "mma.sync.aligned.m16n8k16.row.col.f32.f16.f16.f32 "
        "{%0,%1,%2,%3}, {%4,%5,%6,%7}, {%8,%9}, {%0,%1,%2,%3};"
        : "+f"(c[0]), "+f"(c[1]), "+f"(c[2]), "+f"(c[3])
        : "r"(a[0]), "r"(a[1]), "r"(a[2]), "r"(a[3]), "r"(b[0]), "r"(b[1]));
}

// ---------------------------------------------------------------------------
// prep_x: x[b][c][y][x] fp32 -> padded NHWC fp16 hi/lo: [b][yp 130][xp 130][c]
// ---------------------------------------------------------------------------
__global__ void prep_x(const float* __restrict__ x) {
    __shared__ float tile[64][128];
    const int yp = blockIdx.x;       // 0..129
    const int b = blockIdx.y;
    const int tid = threadIdx.x;
    const bool rowok = (yp >= 1 && yp <= 128);
    if (rowok) {
        const float* src = x + ((size_t)b * 64 * 128 + (yp - 1)) * 128;
        for (int i = tid; i < 8192; i += 256) {
            int c = i >> 7, xx = i & 127;
            tile[c][xx] = src[c * 16384 + xx];
        }
    }
    __syncthreads();
    const size_t obase = ((size_t)b * 130 + yp) * 130 * 64;
    for (int i = tid; i < 130 * 64; i += 256) {
        int xp = i >> 6, c = i & 63;
        float v = 0.f;
        if (rowok && xp >= 1 && xp <= 128) v = tile[c][xp - 1];
        __half hi = __float2half(v);
        __half lo = __float2half(v - __half2float(hi));
        g_xh[obase + i] = hi;
        g_xl[obase + i] = lo;
    }
}

// ---------------------------------------------------------------------------
// prep_w: ew[e][oc][c][dy][dx] -> g_wA[tap][mb][ml][c] fp16 (single plane)
//         ml = eloc*64 + oc,  e = mb*2 + eloc
// ---------------------------------------------------------------------------
__global__ void prep_w(const float* __restrict__ ew) {
    int idx = blockIdx.x * 256 + threadIdx.x;   // < 294912
    int c = idx & 63;
    int ml = (idx >> 6) & 127;
    int mb = (idx >> 13) & 3;
    int tap = idx >> 15;
    int e = mb * 2 + (ml >> 6);
    int oc = ml & 63;
    int dy = tap / 3, dx = tap % 3;
    float w = ew[(((e * 64 + oc) * 64 + c) * 3 + dy) * 3 + dx];
    g_wA[(size_t)(tap * 4 + mb) * 8192 + ml * 64 + c] = __float2half(w);
}

// ---------------------------------------------------------------------------
// gate kernel (proven correct, ~60us)
// ---------------------------------------------------------------------------
__global__ void gate_kernel(const float* __restrict__ x,
                            const float* __restrict__ gate_w,
                            const float* __restrict__ gate_b) {
    const int blk = blockIdx.x;
    const int b = blk >> 8;
    const int ph = (blk >> 4) & 15;
    const int pw = blk & 15;
    const int tid = threadIdx.x;

    float part[8];
#pragma unroll
    for (int e = 0; e < 8; e++) part[e] = 0.f;

    const float* xb = x + ((size_t)b * 64 * 128 + ph * 8) * 128 + pw * 8;

    for (int f = tid; f < 6144; f += 256) {
        int c = f >> 6;
        int r = f & 63;
        float v;
        if (c < 64) {
            int py = r >> 3, px = r & 7;
            v = xb[(c * 128 + py) * 128 + px];
        } else {
            int cc = c - 64;
            int grp = cc >> 3, k = cc & 7;
            float coord = (grp < 2) ? (ph + 0.5f) * (1.f / 16.f)
                                    : (pw + 0.5f) * (1.f / 16.f);
            float ang = coord * ((float)(1 << k) * PI_F);
            v = (grp & 1) ? cosf(ang) : sinf(ang);
        }
#pragma unroll
        for (int e = 0; e < 8; e++) part[e] += v * gate_w[e * 6144 + f];
    }

#pragma unroll
    for (int off = 16; off; off >>= 1) {
#pragma unroll
        for (int e = 0; e < 8; e++)
            part[e] += __shfl_down_sync(0xffffffffu, part[e], off);
    }

    __shared__ float s_red[8][8];
    __shared__ float s_logit[8];
    const int warp = tid >> 5, lane = tid & 31;
    if (lane == 0) {
#pragma unroll
        for (int e = 0; e < 8; e++) s_red[warp][e] = part[e];
    }
    __syncthreads();
    if (tid < 8) {
        float s = gate_b[tid];
#pragma unroll
        for (int w = 0; w < 8; w++) s += s_red[w][tid];
        s_logit[tid] = s;
    }
    __syncthreads();
    if (tid < 8) {
        float m = s_logit[0];
#pragma unroll
        for (int e = 1; e < 8; e++) m = fmaxf(m, s_logit[e]);
        float den = 0.f;
#pragma unroll
        for (int e = 0; e < 8; e++) den += expf(s_logit[e] - m);
        g_gate[blk * 8 + tid] = expf(s_logit[tid] - m) / den;
    }
}

// ---------------------------------------------------------------------------
// conv_mma: HMMA (mma.sync fp16) implicit-GEMM conv + bias + relu + gated
// combine, 2-pass: W_f16 * Xh + W_f16 * Xl (x split hi/lo in fp16).
// CTA = (row y, batch b): N = 128 pixels, M = 128 per phase, 4 mblock
// phases (2 experts each) x 9 taps = 36 double-buffered stages.
// 256 threads = 8 warps, grid 2(M) x 4(N); warp tile M64 x N32.
// Per-phase epilogue folds bias+relu+gate into a 64KB SMEM accumulator
// (per-thread slots, race-free; plane per expert parity). No atomics.
// SMEM (dyn): A0|A1 (16KB ea) | B0|B1 (32KB ea) | acc 64KB.
// Swizzle: 16B chunk j of row r at r*128 + ((j^(r&7))<<4)  (conflict-free
// for cp.async stores and ldmatrix reads).
// ---------------------------------------------------------------------------
static constexpr int B_OFF    = 32768;             // after A0|A1
static constexpr int SACC_OFF = 98304;             // after B0|B1
static constexpr int DSMEM_BYTES = 98304 + 65536 + 1024;   // 164864

__global__ void __launch_bounds__(256, 1)
conv_mma(const float* __restrict__ eb, float* __restrict__ out) {
    extern __shared__ char dsm_raw[];
    __shared__ float sg[1024];      // [e][x]
    __shared__ float sbias[512];    // [e*64+oc]

    const int tid = threadIdx.x;
    const int wid = tid >> 5;
    const int lane = tid & 31;
    const int y = blockIdx.x;
    const int b = blockIdx.y;
    const int wm = wid >> 2;        // 0..1 : M half (64 rows)
    const int wn = wid & 3;         // 0..3 : N quarter (32 px)

    uint32_t base0 = (uint32_t)__cvta_generic_to_shared(dsm_raw);
    const uint32_t base = (base0 + 1023) & ~1023u;
    float* sacc = reinterpret_cast<float*>(dsm_raw + (base - base0) + SACC_OFF);

    for (int i = tid; i < 1024; i += 256) {
        int e = i >> 7, xx = i & 127;
        sg[i] = g_gate[(((b * 16 + (y >> 3)) * 16 + (xx >> 3)) << 3) + e];
    }
    for (int i = tid; i < 512; i += 256) sbias[i] = eb[i];
    for (int i = tid; i < 16384; i += 256) sacc[i] = 0.f;

    auto prefetch = [&](int s) {
        const int mb = s / 9, tap = s % 9;
        // A: W[tap][mb] fp16 single plane, contiguous 16KB in g_wA
        uint32_t abuf = base + (s & 1) * 16384;
        const __half* asrc = g_wA + (size_t)(tap * 4 + mb) * 8192;
        for (int i = tid; i < 1024; i += 256) {
            int row = i >> 3, j = i & 7;          // row = ml (0..127)
            cp16(abuf + row * 128 + ((j ^ (row & 7)) << 4),
                 asrc + row * 64 + j * 8);
        }
        // B: X row (y+dy), pixels dx..dx+127, hi/lo planes
        uint32_t bbuf = base + B_OFF + (s & 1) * 32768;
        const int dy = tap / 3, dx = tap % 3;
        const size_t xoff = (((size_t)b * 130 + (y + dy)) * 130 + dx) * 64;
        for (int i = tid; i < 2048; i += 256) {
            int row = i >> 3, j = i & 7;          // row = plane*128 + pixel
            int plane = row >> 7, p = row & 127;
            const __half* src =
                (plane ? g_xl : g_xh) + xoff + (size_t)p * 64 + j * 8;
            cp16(bbuf + row * 128 + ((j ^ (row & 7)) << 4), src);
        }
        asm volatile("cp.async.commit_group;" ::: "memory");
    };

    float acc[4][4][4];
#pragma unroll
    for (int mt = 0; mt < 4; mt++)
#pragma unroll
        for (int nt = 0; nt < 4; nt++)
#pragma unroll
            for (int v = 0; v < 4; v++) acc[mt][nt][v] = 0.f;

    const int lo4 = lane & 15;      // A: row selector within m16
    const int hi4 = lane >> 4;      // A: k-chunk selector / B: pixel+8 sel

    prefetch(0);

#pragma unroll 1
    for (int s = 0; s < 36; s++) {
        if (s + 1 < 36) {
            prefetch(s + 1);
            asm volatile("cp.async.wait_group 1;" ::: "memory");
        } else {
            asm volatile("cp.async.wait_group 0;" ::: "memory");
        }
        __syncthreads();

        const uint32_t ab = base + (s & 1) * 16384;
        const uint32_t bb = base + B_OFF + (s & 1) * 32768;

#pragma unroll
        for (int kk = 0; kk < 4; kk++) {          // k0 = kk*16
            const int j0 = kk * 2;                // 16B chunk of k0
            uint32_t Aw[4][4];
#pragma unroll
            for (int mt = 0; mt < 4; mt++) {
                int row = wm * 64 + mt * 16 + lo4;
                uint32_t off =
                    row * 128 + (((j0 + hi4) ^ (row & 7)) << 4);
                ldsm4(Aw[mt], ab + off);
            }
            uint32_t Bh[8], Bl[8];
#pragma unroll
            for (int half = 0; half < 2; half++) {
                int p = wn * 32 + half * 16 + (lane & 7) + hi4 * 8;
                int ch = j0 + ((lane >> 3) & 1);
                uint32_t off = p * 128 + ((ch ^ (p & 7)) << 4);
                ldsm4(Bh + half * 4, bb + off);
                ldsm4(Bl + half * 4, bb + 16384 + off);
            }
#pragma unroll
            for (int mt = 0; mt < 4; mt++) {
#pragma unroll
                for (int nt = 0; nt < 4; nt++) {
                    mma16816(acc[mt][nt], Aw[mt], Bh + nt * 2);
                    mma16816(acc[mt][nt], Aw[mt], Bl + nt * 2);
                }
            }
        }
        __syncthreads();

        if (s % 9 == 8) {
            // per-mblock epilogue: bias + relu + gate into sacc, reset acc
            const int mb = s / 9;
#pragma unroll
            for (int mt = 0; mt < 4; mt++) {
                int mrow0 = wm * 64 + mt * 16 + (lane >> 2);
#pragma unroll
                for (int half = 0; half < 2; half++) {
                    int m = mrow0 + half * 8;
                    int eloc = m >> 6, oc = m & 63;
                    int e = mb * 2 + eloc;
                    float bias = sbias[e * 64 + oc];
                    const float* grow = sg + e * 128;
                    float* arow = sacc + eloc * 8192 + oc * 128;
#pragma unroll
                    for (int nt = 0; nt < 4; nt++) {
                        int n = wn * 32 + nt * 8 + (lane & 3) * 2;
                        float v0 = acc[mt][nt][half * 2 + 0];
                        float v1 = acc[mt][nt][half * 2 + 1];
                        arow[n]     += grow[n]     * fmaxf(v0 + bias, 0.f);
                        arow[n + 1] += grow[n + 1] * fmaxf(v1 + bias, 0.f);
                        acc[mt][nt][half * 2 + 0] = 0.f;
                        acc[mt][nt][half * 2 + 1] = 0.f;
                    }
                }
            }
        }
    }

    __syncthreads();
    const size_t ob = (size_t)b * 64 * 16384 + (size_t)y * 128;
    for (int i = tid; i < 2048; i += 256) {     // 64 oc x 32 float4
        int oc2 = i >> 5, j = i & 31;
        const float* r0 = sacc + oc2 * 128 + j * 4;
        const float* r1 = r0 + 8192;
        float4 v;
        v.x = r0[0] + r1[0];
        v.y = r0[1] + r1[1];
        v.z = r0[2] + r1[2];
        v.w = r0[3] + r1[3];
        *reinterpret_cast<float4*>(out + ob + (size_t)oc2 * 16384 + j * 4) = v;
    }
}

extern "C" void kernel_launch(void* const* d_in, const int* in_sizes, int n_in,
                              void* d_out, int out_size) {
    const float* x  = (const float*)d_in[0];   // [16,64,128,128]
    const float* ew = (const float*)d_in[1];   // [8,64,64,3,3]
    const float* eb = (const float*)d_in[2];   // [8,64]
    const float* gw = (const float*)d_in[3];   // [8,6144]
    const float* gb = (const float*)d_in[4];   // [8]
    float* out = (float*)d_out;                // [16,64,128,128]

    static bool attr_set = false;
    if (!attr_set) {
        cudaFuncSetAttribute(conv_mma,
                             cudaFuncAttributeMaxDynamicSharedMemorySize,
                             DSMEM_BYTES);
        attr_set = true;
    }

    prep_x<<<dim3(130, 16), 256>>>(x);
    prep_w<<<1152, 256>>>(ew);
    gate_kernel<<<4096, 256>>>(x, gw, gb);

    dim3 grid(128, 16);   // (row y, batch b)
    conv_mma<<<grid, 256, DSMEM_BYTES>>>(eb, out);
}